// round 1
// baseline (speedup 1.0000x reference)
#include <cuda_runtime.h>
#include <cuda_bf16.h>

#define N_ASSETS   128
#define BATCH      2048
#define N_ITERS    300
#define ROUNDS     20        // 3-probe rounds: 4^20 == 2^40 bracket reduction
#define LR         0.02f
#define EPS        1e-8f
#define CMAX       1.0f

__global__ void __launch_bounds__(256, 2)
markowitz_kernel(const float* __restrict__ rets,
                 const float* __restrict__ cov,
                 const float* __restrict__ gamma,
                 const float* __restrict__ alpha,
                 float* __restrict__ out)
{
    __shared__ __align__(16) float w_sh[N_ASSETS];
    __shared__ float parts_sh[2][N_ASSETS];

    const int b    = blockIdx.x;
    const int t    = threadIdx.x;
    const int i    = t & 127;      // asset row
    const int h    = t >> 7;       // which half of the row's dot product
    const int wid  = t >> 5;
    const int lane = t & 31;

    // ---- load this problem's A = gamma * covmat into registers ----
    const float g = gamma[b];
    const float* Ab = cov + (size_t)b * N_ASSETS * N_ASSETS + (size_t)i * N_ASSETS + h * 64;
    float areg[64];
    #pragma unroll
    for (int k = 0; k < 64; k += 4) {
        float4 c4 = *reinterpret_cast<const float4*>(Ab + k);
        areg[k + 0] = g * c4.x;
        areg[k + 1] = g * c4.y;
        areg[k + 2] = g * c4.z;
        areg[k + 3] = g * c4.w;
    }

    // designated epilogue warp (rotates across SMSPs with blockIdx)
    const int wsel = b & 7;
    float rq0 = 0.f, rq1 = 0.f, rq2 = 0.f, rq3 = 0.f;
    float aab = 0.f;
    if (wid == wsel) {
        const float* rb = rets + (size_t)b * N_ASSETS;
        rq0 = rb[lane +  0];
        rq1 = rb[lane + 32];
        rq2 = rb[lane + 64];
        rq3 = rb[lane + 96];
        aab = fabsf(alpha[b]);
    }

    if (t < N_ASSETS) w_sh[t] = 1.0f / (float)N_ASSETS;
    __syncthreads();

    const float4* w4 = reinterpret_cast<const float4*>(w_sh) + h * 16;

    for (int it = 0; it < N_ITERS; ++it) {
        // ---- half matvec: partial_i = sum_k A[i][64h+k] * w[64h+k] ----
        float a0 = 0.f, a1 = 0.f, a2 = 0.f, a3 = 0.f;
        #pragma unroll
        for (int k = 0; k < 16; ++k) {
            float4 wv = w4[k];                 // broadcast LDS.128
            a0 = fmaf(areg[4 * k + 0], wv.x, a0);
            a1 = fmaf(areg[4 * k + 1], wv.y, a1);
            a2 = fmaf(areg[4 * k + 2], wv.z, a2);
            a3 = fmaf(areg[4 * k + 3], wv.w, a3);
        }
        parts_sh[h][i] = (a0 + a1) + (a2 + a3);
        __syncthreads();

        // ---- epilogue: one warp owns the whole problem (4 assets / lane) ----
        if (wid == wsel) {
            float wq[4], Aq[4], vq[4];
            float pa = 0.f, pw = 0.f;
            #pragma unroll
            for (int q = 0; q < 4; ++q) {
                const int idx = lane + 32 * q;
                wq[q] = w_sh[idx];
                Aq[q] = parts_sh[0][idx] + parts_sh[1][idx];
                pa = fmaf(wq[q], Aq[q], pa);
                pw = fmaf(wq[q], wq[q], pw);
            }
            #pragma unroll
            for (int off = 16; off; off >>= 1) {
                pa += __shfl_xor_sync(0xffffffffu, pa, off);
                pw += __shfl_xor_sync(0xffffffffu, pw, off);
            }
            const float inv_risk = rsqrtf(pa + EPS);
            const float inv_nrm  = rsqrtf(pw + EPS);
            const float an = aab * inv_nrm;

            float vmin =  1e30f, vmax = -1e30f;
            const float r0 = rq0, r1 = rq1, r2 = rq2, r3 = rq3;
            {
                float grad;
                grad = r0 - Aq[0] * inv_risk - an * wq[0];
                vq[0] = fmaf(LR, grad, wq[0]);
                grad = r1 - Aq[1] * inv_risk - an * wq[1];
                vq[1] = fmaf(LR, grad, wq[1]);
                grad = r2 - Aq[2] * inv_risk - an * wq[2];
                vq[2] = fmaf(LR, grad, wq[2]);
                grad = r3 - Aq[3] * inv_risk - an * wq[3];
                vq[3] = fmaf(LR, grad, wq[3]);
            }
            #pragma unroll
            for (int q = 0; q < 4; ++q) {
                vmin = fminf(vmin, vq[q]);
                vmax = fmaxf(vmax, vq[q]);
            }
            #pragma unroll
            for (int off = 16; off; off >>= 1) {
                vmin = fminf(vmin, __shfl_xor_sync(0xffffffffu, vmin, off));
                vmax = fmaxf(vmax, __shfl_xor_sync(0xffffffffu, vmax, off));
            }

            float lo = vmin - CMAX - 1.0f;
            float hi = vmax + CMAX;

            // 3-probe multisection: bracket shrinks 4x per round.
            #pragma unroll 1
            for (int r = 0; r < ROUNDS; ++r) {
                const float qw = 0.25f * (hi - lo);
                const float m1 = lo + qw;
                const float m2 = lo + 2.0f * qw;
                const float m3 = lo + 3.0f * qw;
                float s1 = 0.f, s2 = 0.f, s3 = 0.f;
                #pragma unroll
                for (int q = 0; q < 4; ++q) {
                    const float v = vq[q];
                    s1 += fminf(fmaxf(v - m1, -CMAX), CMAX);
                    s2 += fminf(fmaxf(v - m2, -CMAX), CMAX);
                    s3 += fminf(fmaxf(v - m3, -CMAX), CMAX);
                }
                #pragma unroll
                for (int off = 16; off; off >>= 1) {
                    s1 += __shfl_xor_sync(0xffffffffu, s1, off);
                    s2 += __shfl_xor_sync(0xffffffffu, s2, off);
                    s3 += __shfl_xor_sync(0xffffffffu, s3, off);
                }
                float kf = 0.f;
                if (s1 > 1.0f) kf += 1.0f;
                if (s2 > 1.0f) kf += 1.0f;
                if (s3 > 1.0f) kf += 1.0f;
                lo = fmaf(kf, qw, lo);
                hi = lo + qw;
            }
            const float tau = 0.5f * (lo + hi);
            #pragma unroll
            for (int q = 0; q < 4; ++q) {
                w_sh[lane + 32 * q] = fminf(fmaxf(vq[q] - tau, -CMAX), CMAX);
            }
        }
        __syncthreads();
    }

    if (t < N_ASSETS) out[(size_t)b * N_ASSETS + t] = w_sh[t];
}

extern "C" void kernel_launch(void* const* d_in, const int* in_sizes, int n_in,
                              void* d_out, int out_size)
{
    const float* rets  = (const float*)d_in[0];   // [2048,128]
    const float* cov   = (const float*)d_in[1];   // [2048,128,128]
    const float* gamma = (const float*)d_in[2];   // [2048]
    const float* alpha = (const float*)d_in[3];   // [2048]
    float* out = (float*)d_out;                   // [2048,128]

    markowitz_kernel<<<BATCH, 256>>>(rets, cov, gamma, alpha, out);
}

// round 2
// speedup vs baseline: 1.3340x; 1.3340x over previous
#include <cuda_runtime.h>
#include <cuda_bf16.h>

#define N_ASSETS   128
#define BATCH      2048
#define N_ITERS    300
#define ROUNDS     16        // 3-probe rounds: 4^16 == 2^32 bracket reduction
#define LR         0.02f
#define EPS        1e-8f
#define CMAX       1.0f
#define BR_LO     (-2.5f)    // provably valid constant bracket for tau
#define BR_HI      (2.5f)

// dynamic smem layout (floats):
//   [0 .. 16384)            A (gamma*cov), XOR-swizzled float4 rows
//   [16384 .. 16512)        w
//   [16512 .. 16768)        parts[2][128]
#define SM_A_F4    0
#define SM_W_F     16384
#define SM_P_F     16512
#define SMEM_BYTES ((16384 + 128 + 256) * 4)

__global__ void __launch_bounds__(256, 3)
markowitz_kernel(const float* __restrict__ rets,
                 const float* __restrict__ cov,
                 const float* __restrict__ gamma,
                 const float* __restrict__ alpha,
                 float* __restrict__ out)
{
    extern __shared__ __align__(16) float smem[];
    float4*       A4       = reinterpret_cast<float4*>(smem);          // 4096 float4
    float*        w_sh     = smem + SM_W_F;                            // 128
    float*        parts_sh = smem + SM_P_F;                            // 2*128

    const int b    = blockIdx.x;
    const int t    = threadIdx.x;
    const int i    = t & 127;      // asset row
    const int h    = t >> 7;       // which half of the row's dot product
    const int wid  = t >> 5;
    const int lane = t & 31;

    // ---- stage A = gamma * covmat into shared (XOR-swizzled float4s) ----
    // logical float4 index f = row*32 + c ; physical = f ^ ((f>>5)&7)
    {
        const float g = gamma[b];
        const float4* src = reinterpret_cast<const float4*>(
            cov + (size_t)b * N_ASSETS * N_ASSETS);
        #pragma unroll
        for (int j = 0; j < 16; ++j) {
            const int f = t + 256 * j;               // 0..4095
            float4 c4 = src[f];
            c4.x *= g; c4.y *= g; c4.z *= g; c4.w *= g;
            A4[f ^ ((f >> 5) & 7)] = c4;
        }
    }

    // designated epilogue warp (rotates across SMSPs with blockIdx)
    const int wsel = b & 7;
    float rq0 = 0.f, rq1 = 0.f, rq2 = 0.f, rq3 = 0.f;
    float aab = 0.f;
    if (wid == wsel) {
        const float* rb = rets + (size_t)b * N_ASSETS;
        rq0 = rb[lane +  0];
        rq1 = rb[lane + 32];
        rq2 = rb[lane + 64];
        rq3 = rb[lane + 96];
        aab = fabsf(alpha[b]);
    }

    if (t < N_ASSETS) w_sh[t] = 1.0f / (float)N_ASSETS;
    __syncthreads();

    const int     xi  = i & 7;
    const float4* Ar4 = A4 + i * 32 + h * 16;     // this thread's half-row base
    const float4* w4  = reinterpret_cast<const float4*>(w_sh) + h * 16;

    for (int it = 0; it < N_ITERS; ++it) {
        // ---- half matvec: partial_i = sum_k A[i][64h+k] * w[64h+k] ----
        float a0 = 0.f, a1 = 0.f, a2 = 0.f, a3 = 0.f;
        #pragma unroll
        for (int k = 0; k < 16; ++k) {
            float4 av = Ar4[k ^ xi];           // conflict-free swizzled LDS.128
            float4 wv = w4[k];                 // broadcast LDS.128
            a0 = fmaf(av.x, wv.x, a0);
            a1 = fmaf(av.y, wv.y, a1);
            a2 = fmaf(av.z, wv.z, a2);
            a3 = fmaf(av.w, wv.w, a3);
        }
        parts_sh[h * N_ASSETS + i] = (a0 + a1) + (a2 + a3);
        __syncthreads();

        // ---- epilogue: one warp owns the whole problem (4 assets / lane) ----
        if (wid == wsel) {
            float wq[4], Aq[4], vq[4];
            float pa = 0.f, pw = 0.f;
            #pragma unroll
            for (int q = 0; q < 4; ++q) {
                const int idx = lane + 32 * q;
                wq[q] = w_sh[idx];
                Aq[q] = parts_sh[idx] + parts_sh[N_ASSETS + idx];
                pa = fmaf(wq[q], Aq[q], pa);
                pw = fmaf(wq[q], wq[q], pw);
            }
            #pragma unroll
            for (int off = 16; off; off >>= 1) {
                pa += __shfl_xor_sync(0xffffffffu, pa, off);
                pw += __shfl_xor_sync(0xffffffffu, pw, off);
            }
            const float inv_risk = rsqrtf(pa + EPS);
            const float an       = aab * rsqrtf(pw + EPS);

            vq[0] = fmaf(LR, rq0 - Aq[0] * inv_risk - an * wq[0], wq[0]);
            vq[1] = fmaf(LR, rq1 - Aq[1] * inv_risk - an * wq[1], wq[1]);
            vq[2] = fmaf(LR, rq2 - Aq[2] * inv_risk - an * wq[2], wq[2]);
            vq[3] = fmaf(LR, rq3 - Aq[3] * inv_risk - an * wq[3], wq[3]);

            // constant bracket (provably contains the root; see analysis)
            float lo = BR_LO;
            float hi = BR_HI;

            // 3-probe multisection: bracket shrinks 4x per round.
            #pragma unroll 1
            for (int r = 0; r < ROUNDS; ++r) {
                const float qw = 0.25f * (hi - lo);
                const float m1 = lo + qw;
                const float m2 = lo + 2.0f * qw;
                const float m3 = lo + 3.0f * qw;
                float s1 = 0.f, s2 = 0.f, s3 = 0.f;
                #pragma unroll
                for (int q = 0; q < 4; ++q) {
                    const float v = vq[q];
                    s1 += fminf(fmaxf(v - m1, -CMAX), CMAX);
                    s2 += fminf(fmaxf(v - m2, -CMAX), CMAX);
                    s3 += fminf(fmaxf(v - m3, -CMAX), CMAX);
                }
                #pragma unroll
                for (int off = 16; off; off >>= 1) {
                    s1 += __shfl_xor_sync(0xffffffffu, s1, off);
                    s2 += __shfl_xor_sync(0xffffffffu, s2, off);
                    s3 += __shfl_xor_sync(0xffffffffu, s3, off);
                }
                float kf = 0.f;
                if (s1 > 1.0f) kf += 1.0f;
                if (s2 > 1.0f) kf += 1.0f;
                if (s3 > 1.0f) kf += 1.0f;
                lo = fmaf(kf, qw, lo);
                hi = lo + qw;
            }
            const float tau = 0.5f * (lo + hi);
            #pragma unroll
            for (int q = 0; q < 4; ++q) {
                w_sh[lane + 32 * q] = fminf(fmaxf(vq[q] - tau, -CMAX), CMAX);
            }
        }
        __syncthreads();
    }

    if (t < N_ASSETS) out[(size_t)b * N_ASSETS + t] = w_sh[t];
}

extern "C" void kernel_launch(void* const* d_in, const int* in_sizes, int n_in,
                              void* d_out, int out_size)
{
    const float* rets  = (const float*)d_in[0];   // [2048,128]
    const float* cov   = (const float*)d_in[1];   // [2048,128,128]
    const float* gamma = (const float*)d_in[2];   // [2048]
    const float* alpha = (const float*)d_in[3];   // [2048]
    float* out = (float*)d_out;                   // [2048,128]

    cudaFuncSetAttribute(markowitz_kernel,
                         cudaFuncAttributeMaxDynamicSharedMemorySize, SMEM_BYTES);
    markowitz_kernel<<<BATCH, 256, SMEM_BYTES>>>(rets, cov, gamma, alpha, out);
}

// round 3
// speedup vs baseline: 3.6314x; 2.7221x over previous
#include <cuda_runtime.h>
#include <cuda_bf16.h>

#define N_ASSETS   128
#define BATCH      2048
#define N_ITERS    300
#define ROUNDS     16        // fallback multisection rounds (4^16 == 2^32)
#define LR         0.02f
#define EPS        1e-8f
#define CMAX       1.0f
#define BR_LO     (-2.5f)    // provably valid constant bracket for tau
#define BR_HI      (2.5f)

// dynamic smem layout (floats):
//   [0 .. 16384)            A (gamma*cov), XOR-swizzled float4 rows
//   [16384 .. 16512)        w
//   [16512 .. 16768)        parts[2][128]
#define SM_W_F     16384
#define SM_P_F     16512
#define SMEM_BYTES ((16384 + 128 + 256) * 4)

__global__ void __launch_bounds__(256, 3)
markowitz_kernel(const float* __restrict__ rets,
                 const float* __restrict__ cov,
                 const float* __restrict__ gamma,
                 const float* __restrict__ alpha,
                 float* __restrict__ out)
{
    extern __shared__ __align__(16) float smem[];
    float4* A4       = reinterpret_cast<float4*>(smem);   // 4096 float4
    float*  w_sh     = smem + SM_W_F;                     // 128
    float*  parts_sh = smem + SM_P_F;                     // 2*128

    const int b    = blockIdx.x;
    const int t    = threadIdx.x;
    const int i    = t & 127;      // asset row
    const int h    = t >> 7;       // which half of the row's dot product
    const int wid  = t >> 5;
    const int lane = t & 31;

    // ---- stage A = gamma * covmat into shared (XOR-swizzled float4s) ----
    {
        const float g = gamma[b];
        const float4* src = reinterpret_cast<const float4*>(
            cov + (size_t)b * N_ASSETS * N_ASSETS);
        #pragma unroll
        for (int j = 0; j < 16; ++j) {
            const int f = t + 256 * j;               // 0..4095
            float4 c4 = src[f];
            c4.x *= g; c4.y *= g; c4.z *= g; c4.w *= g;
            A4[f ^ ((f >> 5) & 7)] = c4;
        }
    }

    // designated epilogue warp (rotates across SMSPs with blockIdx)
    const int wsel = b & 7;
    float rq0 = 0.f, rq1 = 0.f, rq2 = 0.f, rq3 = 0.f;
    float aab = 0.f, sum_r = 0.f;
    if (wid == wsel) {
        const float* rb = rets + (size_t)b * N_ASSETS;
        rq0 = rb[lane +  0];
        rq1 = rb[lane + 32];
        rq2 = rb[lane + 64];
        rq3 = rb[lane + 96];
        aab = fabsf(alpha[b]);
        sum_r = ((rq0 + rq1) + (rq2 + rq3));
        #pragma unroll
        for (int off = 16; off; off >>= 1)
            sum_r += __shfl_xor_sync(0xffffffffu, sum_r, off);
    }

    if (t < N_ASSETS) w_sh[t] = 1.0f / (float)N_ASSETS;
    __syncthreads();

    const int     xi  = i & 7;
    const float4* Ar4 = A4 + i * 32 + h * 16;     // this thread's half-row base
    const float4* w4  = reinterpret_cast<const float4*>(w_sh) + h * 16;

    for (int it = 0; it < N_ITERS; ++it) {
        // ---- half matvec: partial_i = sum_k A[i][64h+k] * w[64h+k] ----
        float a0 = 0.f, a1 = 0.f, a2 = 0.f, a3 = 0.f;
        #pragma unroll
        for (int k = 0; k < 16; ++k) {
            float4 av = Ar4[k ^ xi];           // conflict-free swizzled LDS.128
            float4 wv = w4[k];                 // broadcast LDS.128
            a0 = fmaf(av.x, wv.x, a0);
            a1 = fmaf(av.y, wv.y, a1);
            a2 = fmaf(av.z, wv.z, a2);
            a3 = fmaf(av.w, wv.w, a3);
        }
        parts_sh[h * N_ASSETS + i] = (a0 + a1) + (a2 + a3);
        __syncthreads();

        // ---- epilogue: one warp owns the whole problem (4 assets / lane) ----
        if (wid == wsel) {
            float wq[4], Aq[4], vq[4];
            float pa = 0.f, pw = 0.f, sAw = 0.f, sw = 0.f;
            #pragma unroll
            for (int q = 0; q < 4; ++q) {
                const int idx = lane + 32 * q;
                wq[q] = w_sh[idx];
                Aq[q] = parts_sh[idx] + parts_sh[N_ASSETS + idx];
                pa  = fmaf(wq[q], Aq[q], pa);
                pw  = fmaf(wq[q], wq[q], pw);
                sAw += Aq[q];
                sw  += wq[q];
            }
            // fused 4-value butterfly reduction (interleaved trees)
            #pragma unroll
            for (int off = 16; off; off >>= 1) {
                pa  += __shfl_xor_sync(0xffffffffu, pa,  off);
                pw  += __shfl_xor_sync(0xffffffffu, pw,  off);
                sAw += __shfl_xor_sync(0xffffffffu, sAw, off);
                sw  += __shfl_xor_sync(0xffffffffu, sw,  off);
            }
            const float inv_risk = rsqrtf(pa + EPS);
            const float an       = aab * rsqrtf(pw + EPS);

            vq[0] = fmaf(LR, rq0 - Aq[0] * inv_risk - an * wq[0], wq[0]);
            vq[1] = fmaf(LR, rq1 - Aq[1] * inv_risk - an * wq[1], wq[1]);
            vq[2] = fmaf(LR, rq2 - Aq[2] * inv_risk - an * wq[2], wq[2]);
            vq[3] = fmaf(LR, rq3 - Aq[3] * inv_risk - an * wq[3], wq[3]);

            // closed-form tau assuming no element clips:
            // sum(v) = sw + LR*(sum_r - sAw*inv_risk - an*sw)
            const float sv   = sw + LR * (sum_r - sAw * inv_risk - an * sw);
            float tau = (sv - 1.0f) * (1.0f / (float)N_ASSETS);

            // validate: no clipping active at tau0 -> tau0 is the exact root
            float mx = 0.f;
            #pragma unroll
            for (int q = 0; q < 4; ++q)
                mx = fmaxf(mx, fabsf(vq[q] - tau));
            const bool ok = __all_sync(0xffffffffu, mx <= CMAX);

            if (!ok) {
                // rare fallback: 3-probe multisection on constant bracket
                float lo = BR_LO, hi = BR_HI;
                #pragma unroll 1
                for (int r = 0; r < ROUNDS; ++r) {
                    const float qw = 0.25f * (hi - lo);
                    const float m1 = lo + qw;
                    const float m2 = lo + 2.0f * qw;
                    const float m3 = lo + 3.0f * qw;
                    float s1 = 0.f, s2 = 0.f, s3 = 0.f;
                    #pragma unroll
                    for (int q = 0; q < 4; ++q) {
                        const float v = vq[q];
                        s1 += fminf(fmaxf(v - m1, -CMAX), CMAX);
                        s2 += fminf(fmaxf(v - m2, -CMAX), CMAX);
                        s3 += fminf(fmaxf(v - m3, -CMAX), CMAX);
                    }
                    #pragma unroll
                    for (int off = 16; off; off >>= 1) {
                        s1 += __shfl_xor_sync(0xffffffffu, s1, off);
                        s2 += __shfl_xor_sync(0xffffffffu, s2, off);
                        s3 += __shfl_xor_sync(0xffffffffu, s3, off);
                    }
                    float kf = 0.f;
                    if (s1 > 1.0f) kf += 1.0f;
                    if (s2 > 1.0f) kf += 1.0f;
                    if (s3 > 1.0f) kf += 1.0f;
                    lo = fmaf(kf, qw, lo);
                    hi = lo + qw;
                }
                tau = 0.5f * (lo + hi);
            }

            #pragma unroll
            for (int q = 0; q < 4; ++q)
                w_sh[lane + 32 * q] = fminf(fmaxf(vq[q] - tau, -CMAX), CMAX);
        }
        __syncthreads();
    }

    if (t < N_ASSETS) out[(size_t)b * N_ASSETS + t] = w_sh[t];
}

extern "C" void kernel_launch(void* const* d_in, const int* in_sizes, int n_in,
                              void* d_out, int out_size)
{
    const float* rets  = (const float*)d_in[0];   // [2048,128]
    const float* cov   = (const float*)d_in[1];   // [2048,128,128]
    const float* gamma = (const float*)d_in[2];   // [2048]
    const float* alpha = (const float*)d_in[3];   // [2048]
    float* out = (float*)d_out;                   // [2048,128]

    cudaFuncSetAttribute(markowitz_kernel,
                         cudaFuncAttributeMaxDynamicSharedMemorySize, SMEM_BYTES);
    markowitz_kernel<<<BATCH, 256, SMEM_BYTES>>>(rets, cov, gamma, alpha, out);
}

// round 5
// speedup vs baseline: 6.7651x; 1.8629x over previous
#include <cuda_runtime.h>
#include <cuda_bf16.h>

#define N_ASSETS   128
#define BATCH      2048
#define N_ITERS    300
#define ROUNDS     16        // fallback multisection rounds (4^16 == 2^32)
#define LR         0.02f
#define EPS        1e-8f
#define CMAX       1.0f
#define BR_LO     (-2.5f)
#define BR_HI      (2.5f)

typedef unsigned long long ull;

__device__ __forceinline__ ull pack2(float x, float y) {
    ull r; asm("mov.b64 %0, {%1, %2};" : "=l"(r) : "f"(x), "f"(y)); return r;
}
__device__ __forceinline__ ull ffma2(ull a, ull b, ull c) {
    ull r; asm("fma.rn.f32x2 %0, %1, %2, %3;" : "=l"(r) : "l"(a), "l"(b), "l"(c)); return r;
}
__device__ __forceinline__ ull fadd2(ull a, ull b) {
    ull r; asm("add.rn.f32x2 %0, %1, %2;" : "=l"(r) : "l"(a), "l"(b)); return r;
}
__device__ __forceinline__ float2 unpack2(ull v) {
    float2 f; asm("mov.b64 {%0, %1}, %2;" : "=f"(f.x), "=f"(f.y) : "l"(v)); return f;
}

__global__ void __launch_bounds__(256, 2)
markowitz_kernel(const float* __restrict__ rets,
                 const float* __restrict__ cov,
                 const float* __restrict__ gamma,
                 const float* __restrict__ alpha,
                 float* __restrict__ out)
{
    __shared__ __align__(16) float w_sh[N_ASSETS];
    __shared__ float parts_sh[2 * N_ASSETS];

    const int b    = blockIdx.x;
    const int t    = threadIdx.x;
    const int i    = t & 127;      // asset row
    const int h    = t >> 7;       // half of the row's dot product
    const int wid  = t >> 5;
    const int lane = t & 31;

    // ---- A = gamma * covmat into registers as 32 packed f32x2 pairs ----
    // thread (i,h) owns A[i][64h .. 64h+64)
    ull ap[32];
    {
        const float g = gamma[b];
        const float* Ab = cov + (size_t)b * N_ASSETS * N_ASSETS
                              + (size_t)i * N_ASSETS + h * 64;
        #pragma unroll
        for (int k = 0; k < 16; ++k) {
            float4 c4 = *reinterpret_cast<const float4*>(Ab + 4 * k);
            ap[2 * k + 0] = pack2(g * c4.x, g * c4.y);
            ap[2 * k + 1] = pack2(g * c4.z, g * c4.w);
        }
    }

    const int wsel = b & 7;
    float rq0 = 0.f, rq1 = 0.f, rq2 = 0.f, rq3 = 0.f;
    float aab = 0.f, sum_r = 0.f;
    if (wid == wsel) {
        const float* rb = rets + (size_t)b * N_ASSETS;
        rq0 = rb[lane +  0];
        rq1 = rb[lane + 32];
        rq2 = rb[lane + 64];
        rq3 = rb[lane + 96];
        aab = fabsf(alpha[b]);
        sum_r = ((rq0 + rq1) + (rq2 + rq3));
        #pragma unroll
        for (int off = 16; off; off >>= 1)
            sum_r += __shfl_xor_sync(0xffffffffu, sum_r, off);
    }

    if (t < N_ASSETS) w_sh[t] = 1.0f / (float)N_ASSETS;
    __syncthreads();

    // double2 = 16 bytes = 4 floats; this half's 64 floats start at index h*16
    const double2* w2 = reinterpret_cast<const double2*>(w_sh) + h * 16;

    for (int it = 0; it < N_ITERS; ++it) {
        // ---- half matvec via packed dual-fp32 FMA (32 FFMA2 / thread) ----
        ull acc0 = 0ull, acc1 = 0ull;
        #pragma unroll
        for (int k = 0; k < 8; ++k) {
            double2 wd = w2[2 * k];          // float pairs (8k,8k+1),(8k+2,8k+3)
            double2 we = w2[2 * k + 1];      // float pairs (8k+4,..),(8k+6,..)
            acc0 = ffma2(ap[4 * k + 0], __double_as_longlong(wd.x), acc0);
            acc1 = ffma2(ap[4 * k + 1], __double_as_longlong(wd.y), acc1);
            acc0 = ffma2(ap[4 * k + 2], __double_as_longlong(we.x), acc0);
            acc1 = ffma2(ap[4 * k + 3], __double_as_longlong(we.y), acc1);
        }
        float2 s = unpack2(fadd2(acc0, acc1));
        parts_sh[h * N_ASSETS + i] = s.x + s.y;
        __syncthreads();

        // ---- epilogue: one warp owns the whole problem ----
        if (wid == wsel) {
            float wq[4], Aq[4], vq[4];
            float pa = 0.f, pw = 0.f, sAw = 0.f, sw = 0.f;
            #pragma unroll
            for (int q = 0; q < 4; ++q) {
                const int idx = lane + 32 * q;
                wq[q] = w_sh[idx];
                Aq[q] = parts_sh[idx] + parts_sh[N_ASSETS + idx];
                pa  = fmaf(wq[q], Aq[q], pa);
                pw  = fmaf(wq[q], wq[q], pw);
                sAw += Aq[q];
                sw  += wq[q];
            }
            #pragma unroll
            for (int off = 16; off; off >>= 1) {
                pa  += __shfl_xor_sync(0xffffffffu, pa,  off);
                pw  += __shfl_xor_sync(0xffffffffu, pw,  off);
                sAw += __shfl_xor_sync(0xffffffffu, sAw, off);
                sw  += __shfl_xor_sync(0xffffffffu, sw,  off);
            }
            const float inv_risk = rsqrtf(pa + EPS);
            const float an       = aab * rsqrtf(pw + EPS);

            vq[0] = fmaf(LR, rq0 - Aq[0] * inv_risk - an * wq[0], wq[0]);
            vq[1] = fmaf(LR, rq1 - Aq[1] * inv_risk - an * wq[1], wq[1]);
            vq[2] = fmaf(LR, rq2 - Aq[2] * inv_risk - an * wq[2], wq[2]);
            vq[3] = fmaf(LR, rq3 - Aq[3] * inv_risk - an * wq[3], wq[3]);

            // closed-form tau (exact when no element clips)
            const float sv  = sw + LR * (sum_r - sAw * inv_risk - an * sw);
            float tau = (sv - 1.0f) * (1.0f / (float)N_ASSETS);

            float mx = 0.f;
            #pragma unroll
            for (int q = 0; q < 4; ++q)
                mx = fmaxf(mx, fabsf(vq[q] - tau));
            const bool ok = __all_sync(0xffffffffu, mx <= CMAX);

            if (!ok) {
                // rare fallback: 3-probe multisection on constant bracket
                float lo = BR_LO, hi = BR_HI;
                #pragma unroll 1
                for (int r = 0; r < ROUNDS; ++r) {
                    const float qw = 0.25f * (hi - lo);
                    const float m1 = lo + qw;
                    const float m2 = lo + 2.0f * qw;
                    const float m3 = lo + 3.0f * qw;
                    float s1 = 0.f, s2 = 0.f, s3 = 0.f;
                    #pragma unroll
                    for (int q = 0; q < 4; ++q) {
                        const float v = vq[q];
                        s1 += fminf(fmaxf(v - m1, -CMAX), CMAX);
                        s2 += fminf(fmaxf(v - m2, -CMAX), CMAX);
                        s3 += fminf(fmaxf(v - m3, -CMAX), CMAX);
                    }
                    #pragma unroll
                    for (int off = 16; off; off >>= 1) {
                        s1 += __shfl_xor_sync(0xffffffffu, s1, off);
                        s2 += __shfl_xor_sync(0xffffffffu, s2, off);
                        s3 += __shfl_xor_sync(0xffffffffu, s3, off);
                    }
                    float kf = 0.f;
                    if (s1 > 1.0f) kf += 1.0f;
                    if (s2 > 1.0f) kf += 1.0f;
                    if (s3 > 1.0f) kf += 1.0f;
                    lo = fmaf(kf, qw, lo);
                    hi = lo + qw;
                }
                tau = 0.5f * (lo + hi);
            }

            #pragma unroll
            for (int q = 0; q < 4; ++q)
                w_sh[lane + 32 * q] = fminf(fmaxf(vq[q] - tau, -CMAX), CMAX);
        }
        __syncthreads();
    }

    if (t < N_ASSETS) out[(size_t)b * N_ASSETS + t] = w_sh[t];
}

extern "C" void kernel_launch(void* const* d_in, const int* in_sizes, int n_in,
                              void* d_out, int out_size)
{
    const float* rets  = (const float*)d_in[0];   // [2048,128]
    const float* cov   = (const float*)d_in[1];   // [2048,128,128]
    const float* gamma = (const float*)d_in[2];   // [2048]
    const float* alpha = (const float*)d_in[3];   // [2048]
    float* out = (float*)d_out;                   // [2048,128]

    markowitz_kernel<<<BATCH, 256>>>(rets, cov, gamma, alpha, out);
}